// round 3
// baseline (speedup 1.0000x reference)
#include <cuda_runtime.h>

// Problem constants (fixed shapes from reference)
#define D_FEAT 256        // D_IN == D_OUT == 256
#define M_ROWS 100000
#define N_EDGE 1024

// Scratch (no allocations allowed in kernel_launch). 16B-aligned for vector ld/st.
__device__ __align__(16) int   g_S[D_FEAT * D_FEAT];
__device__ __align__(16) float g_Weff[D_FEAT * D_FEAT];
__device__ __align__(16) float g_beff[D_FEAT];

// ---------------------------------------------------------------------------
// packed f32x2 helpers (FFMA2 path — 2x fp32 FMA throughput vs scalar FFMA)
// ---------------------------------------------------------------------------
__device__ __forceinline__ unsigned long long pk2(float x, float y) {
    unsigned long long r;
    asm("mov.b64 %0, {%1, %2};" : "=l"(r) : "f"(x), "f"(y));
    return r;
}
__device__ __forceinline__ void fma2(unsigned long long& d,
                                     unsigned long long a,
                                     unsigned long long b) {
    asm("fma.rn.f32x2 %0, %1, %2, %0;" : "+l"(d) : "l"(a), "l"(b));
}
__device__ __forceinline__ void upk2(unsigned long long v, float& x, float& y) {
    asm("mov.b64 {%0, %1}, %2;" : "=f"(x), "=f"(y) : "l"(v));
}

// ---------------------------------------------------------------------------
// Step 1: zero the edge-count matrix (graph is replayed; must reset each call)
// ---------------------------------------------------------------------------
__global__ void k_zero_S() {
    g_S[blockIdx.x * 256 + threadIdx.x] = 0;
}

// ---------------------------------------------------------------------------
// Step 2: build S[src][dst] += 1 from edge_mapping.
// Dtype-robust: JAX with x64 disabled silently stores int32 even though the
// reference says int64. Sniff the layout: int64 little-endian values < 256
// have every odd int32 word == 0. Indices masked to [0,255] so no input can
// produce an out-of-range atomic. Integer atomics -> exactly deterministic.
// ---------------------------------------------------------------------------
__global__ void k_build_S(const int* __restrict__ em32) {
    __shared__ int is64;
    if (threadIdx.x == 0) {
        int zeros = 0;
        for (int i = 0; i < 64; i++) zeros += (em32[2 * i + 1] == 0);
        is64 = (zeros >= 60);
    }
    __syncthreads();
    int e = threadIdx.x;   // 0..1023
    int src, dst;
    if (is64) {
        src = em32[2 * e];                 // low word of edge_mapping[0][e]
        dst = em32[2 * (N_EDGE + e)];      // low word of edge_mapping[1][e]
    } else {
        src = em32[e];                     // edge_mapping[0][e]
        dst = em32[N_EDGE + e];            // edge_mapping[1][e]
    }
    src &= 255;
    dst &= 255;
    atomicAdd(&g_S[src * D_FEAT + dst], 1);
}

// ---------------------------------------------------------------------------
// Step 3: Weff = (I + S) * W ;  beff = (I + S) * b
// One block per output row o; 256 threads over column i. Deterministic.
// ---------------------------------------------------------------------------
__global__ void k_build_Weff(const float* __restrict__ W,
                             const float* __restrict__ b) {
    __shared__ int   srow[D_FEAT];
    __shared__ float sb[D_FEAT];
    int o = blockIdx.x;
    int i = threadIdx.x;
    srow[i] = g_S[o * D_FEAT + i];
    sb[i]   = b[i];
    __syncthreads();

    float acc = W[o * D_FEAT + i];   // identity part
    for (int j = 0; j < D_FEAT; j++) {
        int s = srow[j];             // warp-uniform -> cheap predicated skip
        if (s != 0) acc += (float)s * W[j * D_FEAT + i];
    }
    g_Weff[o * D_FEAT + i] = acc;

    if (i == 0) {
        float bb = b[o];
        for (int j = 0; j < D_FEAT; j++) bb += (float)srow[j] * sb[j];
        g_beff[o] = bb;
    }
}

// ---------------------------------------------------------------------------
// Step 4: out[m][o] = (sum_i X[m][i] * Weff[o][i] + beff[o]) / batch_lens[m]
// Tiled fp32 GEMM, 128x128x16 block tile, 8x8 microtile, packed f32x2 FMA.
// ---------------------------------------------------------------------------
#define BM 128
#define BN 128
#define BK 16

__global__ __launch_bounds__(256, 2)
void k_gemm(const float* __restrict__ X,
            const float* __restrict__ BL,
            float* __restrict__ out) {
    // +4 pad keeps 16B alignment for LDS.128 while breaking most conflicts
    __shared__ float Xs[BK][BM + 4];
    __shared__ float Ws[BK][BN + 4];

    const int tid = threadIdx.x;
    const int tx  = tid & 15;       // 0..15 -> n microtile
    const int ty  = tid >> 4;       // 0..15 -> m microtile
    const int m0  = blockIdx.x * BM;
    const int n0  = blockIdx.y * BN;

    // global-load mapping: 256 threads, each loads 2 float4 per tile
    const int lr = tid >> 2;          // 0..63  (row within tile)
    const int lc = (tid & 3) * 4;     // 0,4,8,12 (k-col)

    unsigned long long acc[8][4];
#pragma unroll
    for (int i = 0; i < 8; i++)
#pragma unroll
        for (int j = 0; j < 4; j++) acc[i][j] = 0ull;

    for (int kk = 0; kk < D_FEAT; kk += BK) {
        // --- load X tile (with M bound guard) ---
#pragma unroll
        for (int h = 0; h < 2; h++) {
            int m = m0 + lr + h * 64;
            float4 v = make_float4(0.f, 0.f, 0.f, 0.f);
            if (m < M_ROWS)
                v = *(const float4*)&X[(size_t)m * D_FEAT + kk + lc];
            Xs[lc + 0][lr + h * 64] = v.x;
            Xs[lc + 1][lr + h * 64] = v.y;
            Xs[lc + 2][lr + h * 64] = v.z;
            Xs[lc + 3][lr + h * 64] = v.w;
        }
        // --- load Weff tile (n always < 256) ---
#pragma unroll
        for (int h = 0; h < 2; h++) {
            int n = n0 + lr + h * 64;
            float4 v = *(const float4*)&g_Weff[(size_t)n * D_FEAT + kk + lc];
            Ws[lc + 0][lr + h * 64] = v.x;
            Ws[lc + 1][lr + h * 64] = v.y;
            Ws[lc + 2][lr + h * 64] = v.z;
            Ws[lc + 3][lr + h * 64] = v.w;
        }
        __syncthreads();

#pragma unroll
        for (int k = 0; k < BK; k++) {
            float4 a0 = *(const float4*)&Xs[k][ty * 8];
            float4 a1 = *(const float4*)&Xs[k][ty * 8 + 4];
            float4 b0 = *(const float4*)&Ws[k][tx * 8];
            float4 b1 = *(const float4*)&Ws[k][tx * 8 + 4];

            unsigned long long bp[4];
            bp[0] = pk2(b0.x, b0.y);
            bp[1] = pk2(b0.z, b0.w);
            bp[2] = pk2(b1.x, b1.y);
            bp[3] = pk2(b1.z, b1.w);

            float aa[8] = {a0.x, a0.y, a0.z, a0.w, a1.x, a1.y, a1.z, a1.w};
#pragma unroll
            for (int i = 0; i < 8; i++) {
                unsigned long long ap = pk2(aa[i], aa[i]);
#pragma unroll
                for (int j = 0; j < 4; j++) fma2(acc[i][j], ap, bp[j]);
            }
        }
        __syncthreads();
    }

    // --- epilogue: add beff, divide by batch_lens, store float4 ---
    const int nb = n0 + tx * 8;
    float be[8];
#pragma unroll
    for (int j = 0; j < 8; j++) be[j] = g_beff[nb + j];

#pragma unroll
    for (int i = 0; i < 8; i++) {
        int m = m0 + ty * 8 + i;
        if (m >= M_ROWS) continue;
        float inv = 1.0f / BL[m];
        float r[8];
#pragma unroll
        for (int j = 0; j < 4; j++) upk2(acc[i][j], r[2 * j], r[2 * j + 1]);
        float4 o0, o1;
        o0.x = (r[0] + be[0]) * inv;
        o0.y = (r[1] + be[1]) * inv;
        o0.z = (r[2] + be[2]) * inv;
        o0.w = (r[3] + be[3]) * inv;
        o1.x = (r[4] + be[4]) * inv;
        o1.y = (r[5] + be[5]) * inv;
        o1.z = (r[6] + be[6]) * inv;
        o1.w = (r[7] + be[7]) * inv;
        *(float4*)&out[(size_t)m * D_FEAT + nb]     = o0;
        *(float4*)&out[(size_t)m * D_FEAT + nb + 4] = o1;
    }
}

// ---------------------------------------------------------------------------
// Launch: inputs (metadata order): node_features f32, W f32, b f32,
//         edge_mapping (int32 in practice; int64-tolerant), batch_lens f32.
// Output f32 [1, M, 256].
// ---------------------------------------------------------------------------
extern "C" void kernel_launch(void* const* d_in, const int* in_sizes, int n_in,
                              void* d_out, int out_size) {
    const float* X  = (const float*)d_in[0];
    const float* W  = (const float*)d_in[1];
    const float* b  = (const float*)d_in[2];
    const int*   em = (const int*)d_in[3];
    const float* BL = (const float*)d_in[4];
    float* out = (float*)d_out;

    k_zero_S<<<256, 256>>>();
    k_build_S<<<1, N_EDGE>>>(em);
    k_build_Weff<<<256, 256>>>(W, b);

    dim3 grid((M_ROWS + BM - 1) / BM, D_FEAT / BN);
    k_gemm<<<grid, 256>>>(X, BL, out);
}

// round 6
// speedup vs baseline: 1.8629x; 1.8629x over previous
#include <cuda_runtime.h>
#include <cuda_bf16.h>
#include <cstdint>

// Problem constants (fixed shapes from reference)
#define D_FEAT 256
#define M_ROWS 100000
#define N_EDGE 1024

// Scratch (no allocations allowed). 16B-aligned.
__device__ __align__(16) int            g_S[D_FEAT * D_FEAT];
__device__ __align__(16) float          g_Weff[D_FEAT * D_FEAT];
__device__ __align__(16) float          g_beff[D_FEAT];
__device__ __align__(16) __nv_bfloat16  g_Whi[D_FEAT * D_FEAT];
__device__ __align__(16) __nv_bfloat16  g_Wlo[D_FEAT * D_FEAT];

// ---------------------------------------------------------------------------
// Prologue kernels (unchanged from the passing R3 kernel)
// ---------------------------------------------------------------------------
__global__ void k_zero_S() { g_S[blockIdx.x * 256 + threadIdx.x] = 0; }

__global__ void k_build_S(const int* __restrict__ em32) {
    __shared__ int is64;
    if (threadIdx.x == 0) {
        int zeros = 0;
        for (int i = 0; i < 64; i++) zeros += (em32[2 * i + 1] == 0);
        is64 = (zeros >= 60);
    }
    __syncthreads();
    int e = threadIdx.x;
    int src, dst;
    if (is64) { src = em32[2 * e];  dst = em32[2 * (N_EDGE + e)]; }
    else      { src = em32[e];      dst = em32[N_EDGE + e]; }
    src &= 255; dst &= 255;
    atomicAdd(&g_S[src * D_FEAT + dst], 1);
}

__global__ void k_build_Weff(const float* __restrict__ W, const float* __restrict__ b) {
    __shared__ int   srow[D_FEAT];
    __shared__ float sb[D_FEAT];
    int o = blockIdx.x, i = threadIdx.x;
    srow[i] = g_S[o * D_FEAT + i];
    sb[i]   = b[i];
    __syncthreads();
    float acc = W[o * D_FEAT + i];
    for (int j = 0; j < D_FEAT; j++) {
        int s = srow[j];
        if (s != 0) acc += (float)s * W[j * D_FEAT + i];
    }
    g_Weff[o * D_FEAT + i] = acc;
    if (i == 0) {
        float bb = b[o];
        for (int j = 0; j < D_FEAT; j++) bb += (float)srow[j] * sb[j];
        g_beff[o] = bb;
    }
}

__global__ void k_split_W() {
    int o = blockIdx.x, i = threadIdx.x;
    float x = g_Weff[o * D_FEAT + i];
    __nv_bfloat16 h = __float2bfloat16_rn(x);
    __nv_bfloat16 l = __float2bfloat16_rn(x - __bfloat162float(h));
    g_Whi[o * D_FEAT + i] = h;
    g_Wlo[o * D_FEAT + i] = l;
}

// ---------------------------------------------------------------------------
// HMMA GEMM (warp-level mma.sync, split-bf16 x3 fp32 emulation)
//   out[m][n] = (sum_k X[m][k]*Weff[n][k] + beff[n]) / BL[m]
// CTA tile 128x128, BK=32, 8 warps (4m x 2n), warp tile 32x64.
// ---------------------------------------------------------------------------
#define BK 32
#define A_HI 0
#define A_LO 8192
#define B_HI 16384
#define B_LO 24576
#define BUFB 32768
#define SMEMB (2 * BUFB)

// Conflict-free swizzle for 64-byte rows: XOR 16B-chunk index with row/2 (mod 4)
__device__ __forceinline__ uint32_t swz64(uint32_t off) {
    return off ^ (((off >> 7) & 3u) << 4);
}
__device__ __forceinline__ void ldsm4(uint32_t* r, uint32_t addr) {
    asm volatile("ldmatrix.sync.aligned.m8n8.x4.shared.b16 {%0,%1,%2,%3}, [%4];"
                 : "=r"(r[0]), "=r"(r[1]), "=r"(r[2]), "=r"(r[3]) : "r"(addr));
}
__device__ __forceinline__ void mma_bf16(float* c, const uint32_t* a,
                                         uint32_t b0, uint32_t b1) {
    asm volatile(
        "mma.sync.aligned.m16n8k16.row.col.f32.bf16.bf16.f32 "
        "{%0,%1,%2,%3}, {%4,%5,%6,%7}, {%8,%9}, {%0,%1,%2,%3};"
        : "+f"(c[0]), "+f"(c[1]), "+f"(c[2]), "+f"(c[3])
        : "r"(a[0]), "r"(a[1]), "r"(a[2]), "r"(a[3]), "r"(b0), "r"(b1));
}

__device__ __forceinline__ void load_A(float4* xa, const float* __restrict__ X,
                                       int m0, int kk, int tid) {
    const int u = tid & 7, r0 = tid >> 3;
#pragma unroll
    for (int p = 0; p < 4; p++) {
        int m = m0 + r0 + p * 32;
        xa[p] = (m < M_ROWS) ? *(const float4*)&X[(size_t)m * D_FEAT + kk + u * 4]
                             : make_float4(0.f, 0.f, 0.f, 0.f);
    }
}
__device__ __forceinline__ void load_B(uint4* bh, uint4* bl, int n0, int kk, int tid) {
    const int u = tid & 3, r0 = tid >> 2;
#pragma unroll
    for (int p = 0; p < 2; p++) {
        int n = n0 + r0 + p * 64;
        bh[p] = *(const uint4*)&g_Whi[n * D_FEAT + kk + u * 8];
        bl[p] = *(const uint4*)&g_Wlo[n * D_FEAT + kk + u * 8];
    }
}
__device__ __forceinline__ void store_A(char* buf, const float4* xa, int tid) {
    const int u = tid & 7, r0 = tid >> 3;
#pragma unroll
    for (int p = 0; p < 4; p++) {
        float xs[4] = {xa[p].x, xa[p].y, xa[p].z, xa[p].w};
        unsigned hh[4], ll[4];
#pragma unroll
        for (int e = 0; e < 4; e++) {
            __nv_bfloat16 hb = __float2bfloat16_rn(xs[e]);
            __nv_bfloat16 lb = __float2bfloat16_rn(xs[e] - __bfloat162float(hb));
            hh[e] = (unsigned)__bfloat16_as_ushort(hb);
            ll[e] = (unsigned)__bfloat16_as_ushort(lb);
        }
        uint2 ph = make_uint2(hh[0] | (hh[1] << 16), hh[2] | (hh[3] << 16));
        uint2 pl = make_uint2(ll[0] | (ll[1] << 16), ll[2] | (ll[3] << 16));
        int r = r0 + p * 32;
        uint32_t sw = swz64((uint32_t)(r * 64 + (u >> 1) * 16)) + (u & 1) * 8;
        *(uint2*)(buf + A_HI + sw) = ph;
        *(uint2*)(buf + A_LO + sw) = pl;
    }
}
__device__ __forceinline__ void store_B(char* buf, const uint4* bh, const uint4* bl,
                                        int tid) {
    const int u = tid & 3, r0 = tid >> 2;
#pragma unroll
    for (int p = 0; p < 2; p++) {
        int r = r0 + p * 64;
        uint32_t sw = swz64((uint32_t)(r * 64 + u * 16));
        *(uint4*)(buf + B_HI + sw) = bh[p];
        *(uint4*)(buf + B_LO + sw) = bl[p];
    }
}

__device__ __forceinline__ void compute_buf(uint32_t sbuf, float acc[2][8][4],
                                            int lane, int wm, int wn) {
#pragma unroll
    for (int s = 0; s < 2; s++) {
        uint32_t ah[2][4], al[2][4];
#pragma unroll
        for (int i = 0; i < 2; i++) {
            uint32_t row = (uint32_t)(wm * 32 + i * 16 + (lane & 15));
            uint32_t sw = swz64(row * 64 + s * 32 + ((lane >> 4) << 4));
            ldsm4(ah[i], sbuf + A_HI + sw);
            ldsm4(al[i], sbuf + A_LO + sw);
        }
#pragma unroll
        for (int g = 0; g < 4; g++) {
            uint32_t row = (uint32_t)(wn * 64 + g * 16 + (lane & 7) + ((lane >> 4) << 3));
            uint32_t sw = swz64(row * 64 + s * 32 + (((lane >> 3) & 1) << 4));
            uint32_t bh[4], bl[4];
            ldsm4(bh, sbuf + B_HI + sw);
            ldsm4(bl, sbuf + B_LO + sw);
#pragma unroll
            for (int i = 0; i < 2; i++)
#pragma unroll
                for (int jj = 0; jj < 2; jj++) {
                    float* c = acc[i][g * 2 + jj];
                    mma_bf16(c, ah[i], bh[jj * 2], bh[jj * 2 + 1]);  // hi*hi
                    mma_bf16(c, ah[i], bl[jj * 2], bl[jj * 2 + 1]);  // hi*lo
                    mma_bf16(c, al[i], bh[jj * 2], bh[jj * 2 + 1]);  // lo*hi
                }
        }
    }
}

__global__ __launch_bounds__(256, 1)
void k_gemm_mma(const float* __restrict__ X,
                const float* __restrict__ BL,
                float* __restrict__ out) {
    extern __shared__ __align__(128) char smem[];
    const uint32_t sb = (uint32_t)__cvta_generic_to_shared(smem);
    const int tid  = threadIdx.x;
    const int lane = tid & 31;
    const int w    = tid >> 5;
    const int wm   = w & 3;    // 4 m-groups of 32 rows
    const int wn   = w >> 2;   // 2 n-groups of 64 cols
    const int m0   = blockIdx.x * 128;
    const int n0   = blockIdx.y * 128;

    float acc[2][8][4];
#pragma unroll
    for (int i = 0; i < 2; i++)
#pragma unroll
        for (int j = 0; j < 8; j++)
#pragma unroll
            for (int q = 0; q < 4; q++) acc[i][j][q] = 0.f;

    float4 xa[4];
    uint4  bvh[2], bvl[2];

    // prologue fill of buffer 0
    load_A(xa, X, m0, 0, tid);
    load_B(bvh, bvl, n0, 0, tid);
    store_A(smem, xa, tid);
    store_B(smem, bvh, bvl, tid);
    __syncthreads();

#pragma unroll 1
    for (int kt = 0; kt < 8; kt++) {
        if (kt < 7) {
            load_A(xa, X, m0, (kt + 1) * BK, tid);
            load_B(bvh, bvl, n0, (kt + 1) * BK, tid);
        }
        compute_buf(sb + (kt & 1) * BUFB, acc, lane, wm, wn);
        if (kt < 7) {
            char* nb = smem + ((kt + 1) & 1) * BUFB;
            store_A(nb, xa, tid);
            store_B(nb, bvh, bvl, tid);
            __syncthreads();
        }
    }

    // epilogue: c0,c1 -> row t/4; c2,c3 -> row t/4+8; cols (lane&3)*2,+1
    const int mbase = m0 + wm * 32;
#pragma unroll
    for (int i = 0; i < 2; i++) {
        int r0 = mbase + i * 16 + (lane >> 2);
        int r1 = r0 + 8;
        float inv0 = (r0 < M_ROWS) ? (1.0f / BL[r0]) : 0.f;
        float inv1 = (r1 < M_ROWS) ? (1.0f / BL[r1]) : 0.f;
#pragma unroll
        for (int j = 0; j < 8; j++) {
            int col = n0 + wn * 64 + j * 8 + (lane & 3) * 2;
            float b0 = __ldg(&g_beff[col]);
            float b1 = __ldg(&g_beff[col + 1]);
            const float* c = acc[i][j];
            if (r0 < M_ROWS) {
                float2 o = make_float2((c[0] + b0) * inv0, (c[1] + b1) * inv0);
                *(float2*)&out[(size_t)r0 * D_FEAT + col] = o;
            }
            if (r1 < M_ROWS) {
                float2 o = make_float2((c[2] + b0) * inv1, (c[3] + b1) * inv1);
                *(float2*)&out[(size_t)r1 * D_FEAT + col] = o;
            }
        }
    }
}

// ---------------------------------------------------------------------------
// Launch
// ---------------------------------------------------------------------------
extern "C" void kernel_launch(void* const* d_in, const int* in_sizes, int n_in,
                              void* d_out, int out_size) {
    const float* X  = (const float*)d_in[0];
    const float* W  = (const float*)d_in[1];
    const float* b  = (const float*)d_in[2];
    const int*   em = (const int*)d_in[3];
    const float* BL = (const float*)d_in[4];
    float* out = (float*)d_out;

    cudaFuncSetAttribute(k_gemm_mma, cudaFuncAttributeMaxDynamicSharedMemorySize,
                         SMEMB);

    k_zero_S<<<256, 256>>>();
    k_build_S<<<1, N_EDGE>>>(em);
    k_build_Weff<<<256, 256>>>(W, b);
    k_split_W<<<256, 256>>>();

    dim3 grid((M_ROWS + 127) / 128, 2);   // 782 x 2
    k_gemm_mma<<<grid, 256, SMEMB>>>(X, BL, out);
}